// round 4
// baseline (speedup 1.0000x reference)
#include <cuda_runtime.h>

// GRU fused recurrence, fp32 SIMT.
// Layout: grid = 256 CTAs x 16 batch rows; block = 160 threads, thread = output
// column k (k<150 active). Weights via __ldg (L1-resident, warp-coalesced);
// x tile + h state in SMEM, read as broadcast LDS.128; x prefetched one step
// ahead into registers. 3 __syncthreads per step.

#define TT   128
#define FF   64
#define NU   50
#define K3   150
#define BR   16
#define NTHR 160
#define HP   52   // h row pitch (floats), 16B-aligned rows

__device__ __forceinline__ float sigmoidf_(float v) {
    return __fdividef(1.0f, 1.0f + __expf(-v));
}

__global__ __launch_bounds__(NTHR, 2) void gru_fused_kernel(
    const float* __restrict__ x,    // [4096,128,64]
    const float* __restrict__ W,    // [64,150]
    const float* __restrict__ U,    // [50,150]
    const float* __restrict__ bvec, // [2,150]
    const float* __restrict__ Wd,   // [50,1]
    const float* __restrict__ bd,   // [1]
    float* __restrict__ out)        // [4096,1]
{
    __shared__ __align__(16) float sx[BR * FF];  // [r][f], pitch 64
    __shared__ __align__(16) float sh[BR * HP];  // [r][j], pitch 52
    __shared__ float sgr[BR * NU];               // r-gate exchange [r][j]
    __shared__ float shc[BR * NU];               // hcand exchange  [r][j]

    const int tid  = threadIdx.x;
    const int k    = tid;              // output column this thread owns
    const int brow = blockIdx.x * BR;  // first batch row of this CTA

    // h0 = 0 (padded cols 50..51 stay 0 forever)
    for (int i = tid; i < BR * HP; i += NTHR) sh[i] = 0.0f;

    float b0k = 0.0f, b1k = 0.0f;
    if (k < K3) { b0k = __ldg(&bvec[k]); b1k = __ldg(&bvec[K3 + k]); }

    // prefetch x tile for t = 0 into registers
    float xr[7];
    #pragma unroll
    for (int i = 0; i < 7; i++) {
        int idx = tid + i * NTHR;
        if (idx < BR * FF) {
            int r = idx >> 6, f = idx & 63;
            xr[i] = __ldg(&x[(size_t)(brow + r) * (TT * FF) + f]);
        }
    }
    __syncthreads();  // h init visible

    for (int t = 0; t < TT; t++) {
        // commit prefetched x tile to SMEM
        #pragma unroll
        for (int i = 0; i < 7; i++) {
            int idx = tid + i * NTHR;
            if (idx < BR * FF) sx[idx] = xr[i];
        }
        __syncthreads();  // (a) sx ready; previous step's h writes ready

        // issue next step's global loads now (latency hidden by this step)
        if (t + 1 < TT) {
            #pragma unroll
            for (int i = 0; i < 7; i++) {
                int idx = tid + i * NTHR;
                if (idx < BR * FF) {
                    int r = idx >> 6, f = idx & 63;
                    xr[i] = __ldg(&x[(size_t)(brow + r) * (TT * FF)
                                     + (size_t)(t + 1) * FF + f]);
                }
            }
        }

        float accX[BR], accH[BR];
        #pragma unroll
        for (int r = 0; r < BR; r++) { accX[r] = b0k; accH[r] = b1k; }

        if (k < K3) {
            // xp[r][k] = b0[k] + sum_f x[r][f] * W[f][k]
            #pragma unroll
            for (int fg = 0; fg < FF / 4; fg++) {
                const int f0 = fg * 4;
                float w0 = __ldg(&W[(f0 + 0) * K3 + k]);
                float w1 = __ldg(&W[(f0 + 1) * K3 + k]);
                float w2 = __ldg(&W[(f0 + 2) * K3 + k]);
                float w3 = __ldg(&W[(f0 + 3) * K3 + k]);
                #pragma unroll
                for (int r = 0; r < BR; r++) {
                    float4 xv = *(const float4*)(sx + r * FF + f0);  // broadcast
                    accX[r] = fmaf(xv.x, w0, accX[r]);
                    accX[r] = fmaf(xv.y, w1, accX[r]);
                    accX[r] = fmaf(xv.z, w2, accX[r]);
                    accX[r] = fmaf(xv.w, w3, accX[r]);
                }
            }
            // hp[r][k] = b1[k] + sum_j h[r][j] * U[j][k]   (j = 0..49)
            #pragma unroll
            for (int jg = 0; jg < 12; jg++) {
                const int j0 = jg * 4;
                float u0 = __ldg(&U[(j0 + 0) * K3 + k]);
                float u1 = __ldg(&U[(j0 + 1) * K3 + k]);
                float u2 = __ldg(&U[(j0 + 2) * K3 + k]);
                float u3 = __ldg(&U[(j0 + 3) * K3 + k]);
                #pragma unroll
                for (int r = 0; r < BR; r++) {
                    float4 hv = *(const float4*)(sh + r * HP + j0);  // broadcast
                    accH[r] = fmaf(hv.x, u0, accH[r]);
                    accH[r] = fmaf(hv.y, u1, accH[r]);
                    accH[r] = fmaf(hv.z, u2, accH[r]);
                    accH[r] = fmaf(hv.w, u3, accH[r]);
                }
            }
            {   // tail j = 48, 49
                float u0 = __ldg(&U[48 * K3 + k]);
                float u1 = __ldg(&U[49 * K3 + k]);
                #pragma unroll
                for (int r = 0; r < BR; r++) {
                    float2 hv = *(const float2*)(sh + r * HP + 48);
                    accH[r] = fmaf(hv.x, u0, accH[r]);
                    accH[r] = fmaf(hv.y, u1, accH[r]);
                }
            }
        }

        // gates: k in [50,100) -> r gate; k in [0,50) -> z; k in [100,150) -> hcand
        float zv[BR];
        if (k >= NU && k < 2 * NU) {
            const int j = k - NU;
            #pragma unroll
            for (int r = 0; r < BR; r++)
                sgr[r * NU + j] = sigmoidf_(accX[r] + accH[r]);
        }
        if (k < NU) {
            #pragma unroll
            for (int r = 0; r < BR; r++)
                zv[r] = sigmoidf_(accX[r] + accH[r]);
        }
        __syncthreads();  // (b) sgr ready

        if (k >= 2 * NU && k < K3) {
            const int j = k - 2 * NU;
            #pragma unroll
            for (int r = 0; r < BR; r++) {
                float pre = accX[r] + sgr[r * NU + j] * accH[r];
                shc[r * NU + j] = fmaxf(pre, 0.0f);
            }
        }
        __syncthreads();  // (c) shc ready

        if (k < NU) {
            const int j = k;
            #pragma unroll
            for (int r = 0; r < BR; r++) {
                float hold = sh[r * HP + j];
                sh[r * HP + j] = zv[r] * hold + (1.0f - zv[r]) * shc[r * NU + j];
            }
        }
        // no trailing barrier: next iteration's barrier (a) orders sh
        // writes before the next accumulation reads.
    }

    __syncthreads();  // final h visible
    if (tid < BR) {
        float acc = __ldg(&bd[0]);
        #pragma unroll
        for (int j = 0; j < NU; j++)
            acc += sh[tid * HP + j] * __ldg(&Wd[j]);
        out[brow + tid] = acc;
    }
}

extern "C" void kernel_launch(void* const* d_in, const int* in_sizes, int n_in,
                              void* d_out, int out_size) {
    (void)in_sizes; (void)n_in; (void)out_size;
    const float* x    = (const float*)d_in[0];
    const float* W    = (const float*)d_in[1];
    const float* U    = (const float*)d_in[2];
    const float* bvec = (const float*)d_in[3];
    const float* Wd   = (const float*)d_in[4];
    const float* bd   = (const float*)d_in[5];
    float* out = (float*)d_out;

    gru_fused_kernel<<<4096 / BR, NTHR>>>(x, W, U, bvec, Wd, bd, out);
}